// round 6
// baseline (speedup 1.0000x reference)
#include <cuda_runtime.h>

// RoPE over x:(B=4, H=32, S=8192, D=64) fp32, token_position = arange(S).
// Persistent fused kernel: 1184 blocks (148 SMs x 8), each block loops over
// sequence positions s. Per position:
//   - threads 0..31 compute the 32 (cos,sin) pairs into a double-buffered
//     smem slot (double-precision range reduction -> fast sincosf path).
//   - all 256 threads stream the B*H = 128 rows (2048 float4s), cs held in
//     registers. One __syncthreads per position (double buffer makes the
//     write->read->rewrite sequence race-free).

#define S_LEN   8192
#define HALF_D  32
#define LOG2_THETA 13.287712379549449     // log2(10000)
#define TWO_PI    6.283185307179586476925
#define INV_2PI   0.159154943091895335769

#define GRID_BLOCKS (148 * 8)

__global__ void __launch_bounds__(256)
rope_persistent(const float4* __restrict__ x, float4* __restrict__ out,
                const int* __restrict__ token_position, int P)
{
    __shared__ float2 cs_sh[2][HALF_D];

    int tid    = threadIdx.x;
    int within = tid & 15;            // float4 index within 64-elem row
    int bh0    = tid >> 4;            // 0..15
    const int rstride = 16 * S_LEN * 16;  // +16 rows, in float4 units

    int p = 0;
    for (int s = blockIdx.x; s < P; s += gridDim.x, p ^= 1) {
        if (tid < HALF_D) {
            float pos = (float)token_position[s];
            float inv = (float)exp2(-(double)(2 * tid) / 64.0 * LOG2_THETA);
            float ang = pos * inv;                  // fp32 angle, ref rounding
            double a = (double)ang;
            double k = rint(a * INV_2PI);
            float  r = (float)(a - k * TWO_PI);     // |r| <= pi
            float sn, cn;
            sincosf(r, &sn, &cn);
            cs_sh[p][tid] = make_float2(cn, sn);
        }
        __syncthreads();

        float4 cs = reinterpret_cast<const float4*>(cs_sh[p])[within];
        int base = bh0 * (S_LEN * 16) + s * 16 + within;

        #pragma unroll
        for (int batch = 0; batch < 2; batch++) {
            int i0 = base + batch * (4 * rstride);
            float4 v0 = x[i0];
            float4 v1 = x[i0 + rstride];
            float4 v2 = x[i0 + 2 * rstride];
            float4 v3 = x[i0 + 3 * rstride];

            float4 r0, r1, r2, r3;
            r0.x = v0.x * cs.x - v0.y * cs.y;  r0.y = v0.x * cs.y + v0.y * cs.x;
            r0.z = v0.z * cs.z - v0.w * cs.w;  r0.w = v0.z * cs.w + v0.w * cs.z;
            r1.x = v1.x * cs.x - v1.y * cs.y;  r1.y = v1.x * cs.y + v1.y * cs.x;
            r1.z = v1.z * cs.z - v1.w * cs.w;  r1.w = v1.z * cs.w + v1.w * cs.z;
            r2.x = v2.x * cs.x - v2.y * cs.y;  r2.y = v2.x * cs.y + v2.y * cs.x;
            r2.z = v2.z * cs.z - v2.w * cs.w;  r2.w = v2.z * cs.w + v2.w * cs.z;
            r3.x = v3.x * cs.x - v3.y * cs.y;  r3.y = v3.x * cs.y + v3.y * cs.x;
            r3.z = v3.z * cs.z - v3.w * cs.w;  r3.w = v3.z * cs.w + v3.w * cs.z;

            out[i0]               = r0;
            out[i0 + rstride]     = r1;
            out[i0 + 2 * rstride] = r2;
            out[i0 + 3 * rstride] = r3;
        }
        // Note: reads of cs_sh[p] (into registers) in this iteration are
        // separated from the next write of cs_sh[p] (two iterations later)
        // by the __syncthreads of the next iteration -> no extra barrier.
    }
}

extern "C" void kernel_launch(void* const* d_in, const int* in_sizes, int n_in,
                              void* d_out, int out_size) {
    const float* x   = (const float*)d_in[0];
    const int*   tok = (const int*)d_in[1];
    int P = in_sizes[1];               // 8192 positions (== S)

    rope_persistent<<<GRID_BLOCKS, 256>>>((const float4*)x, (float4*)d_out, tok, P);
}

// round 7
// speedup vs baseline: 1.0919x; 1.0919x over previous
#include <cuda_runtime.h>

// RoPE over x:(B=4, H=32, S=8192, D=64) fp32, token_position = arange(S).
// Fused kernel, tile = (16 bh rows) x (16 s positions) per block:
//   - every thread computes 2 (cos,sin) pairs -> smem (512 pairs per block),
//     double-precision range reduction -> fast sincosf path (matches the
//     fp32 JAX reference to ~2 ulp).
//   - each thread owns (s_local = tid>>4, within = tid&15); its cs float4 is
//     loop-invariant -> registers. Block streams 4 KB CONTIGUOUS per bh
//     iteration (16 s x 256 B) for good DRAM row-buffer locality, 16 bh
//     iterations at 2 MB stride, MLP=4 batching.

#define S_LEN   8192
#define HALF_D  32
#define LOG2_THETA 13.287712379549449     // log2(10000)
#define TWO_PI    6.283185307179586476925
#define INV_2PI   0.159154943091895335769

#define S_TILE   16
#define BH_TILE  16

__global__ void __launch_bounds__(256)
rope_tiled(const float4* __restrict__ x, float4* __restrict__ out,
           const int* __restrict__ token_position, int s_tiles)
{
    __shared__ float2 cs_sh[S_TILE * HALF_D];   // 512 pairs

    int tid = threadIdx.x;
    int s_base  = (blockIdx.x % s_tiles) * S_TILE;
    int bh_base = (blockIdx.x / s_tiles) * BH_TILE;

    // Each thread computes 2 of the 512 (cos,sin) pairs.
    #pragma unroll
    for (int q = tid; q < S_TILE * HALF_D; q += 256) {
        int sl = q >> 5;          // s within tile
        int j  = q & 31;          // frequency index
        float pos = (float)token_position[s_base + sl];
        float inv = (float)exp2(-(double)(2 * j) / 64.0 * LOG2_THETA);
        float ang = pos * inv;                    // fp32 angle, ref rounding
        double a = (double)ang;
        double k = rint(a * INV_2PI);
        float  r = (float)(a - k * TWO_PI);       // |r| <= pi
        float sn, cn;
        sincosf(r, &sn, &cn);
        cs_sh[q] = make_float2(cn, sn);
    }
    __syncthreads();

    int within  = tid & 15;       // float4 index within 64-elem row
    int s_local = tid >> 4;       // 0..15
    // float4 view: element tid == pairs (2*tid, 2*tid+1) == (s_local, 2*within)
    float4 cs = reinterpret_cast<const float4*>(cs_sh)[tid];

    const int stride = S_LEN * 16;                      // +1 bh, float4 units
    int base = bh_base * stride + (s_base + s_local) * 16 + within;

    #pragma unroll
    for (int batch = 0; batch < BH_TILE / 4; batch++) {
        int i0 = base + batch * (4 * stride);
        float4 v0 = x[i0];
        float4 v1 = x[i0 + stride];
        float4 v2 = x[i0 + 2 * stride];
        float4 v3 = x[i0 + 3 * stride];

        float4 r0, r1, r2, r3;
        r0.x = v0.x * cs.x - v0.y * cs.y;  r0.y = v0.x * cs.y + v0.y * cs.x;
        r0.z = v0.z * cs.z - v0.w * cs.w;  r0.w = v0.z * cs.w + v0.w * cs.z;
        r1.x = v1.x * cs.x - v1.y * cs.y;  r1.y = v1.x * cs.y + v1.y * cs.x;
        r1.z = v1.z * cs.z - v1.w * cs.w;  r1.w = v1.z * cs.w + v1.w * cs.z;
        r2.x = v2.x * cs.x - v2.y * cs.y;  r2.y = v2.x * cs.y + v2.y * cs.x;
        r2.z = v2.z * cs.z - v2.w * cs.w;  r2.w = v2.z * cs.w + v2.w * cs.z;
        r3.x = v3.x * cs.x - v3.y * cs.y;  r3.y = v3.x * cs.y + v3.y * cs.x;
        r3.z = v3.z * cs.z - v3.w * cs.w;  r3.w = v3.z * cs.w + v3.w * cs.z;

        out[i0]              = r0;
        out[i0 + stride]     = r1;
        out[i0 + 2 * stride] = r2;
        out[i0 + 3 * stride] = r3;
    }
}

extern "C" void kernel_launch(void* const* d_in, const int* in_sizes, int n_in,
                              void* d_out, int out_size) {
    const float* x   = (const float*)d_in[0];
    const int*   tok = (const int*)d_in[1];
    int n = in_sizes[0];           // 67,108,864 elements
    int P = in_sizes[1];           // 8192 positions (== S)
    int nrows   = n / (P * 64);    // B*H = 128
    int s_tiles = P / S_TILE;      // 512
    int blocks  = s_tiles * (nrows / BH_TILE);  // 4096

    rope_tiled<<<blocks, 256>>>((const float4*)x, (float4*)d_out, tok, s_tiles);
}

// round 8
// speedup vs baseline: 1.1490x; 1.0523x over previous
#include <cuda_runtime.h>

// RoPE over x:(B=4, H=32, S=8192, D=64) fp32, token_position = arange(S).
// Fused kernel: one block = 2 consecutive sequence positions, 512 threads.
//   - threads 0..63 compute the 64 (cos,sin) pairs for (s0, s0+1) into smem
//     (double-precision range reduction -> fast sincosf; matches the fp32
//     JAX reference to ~2 ulp).
//   - warp mapping (within = tid&15, sl = (tid>>4)&1, bh0 = tid>>5): each
//     warp's LDG.128/STG.128 covers one CONTIGUOUS 512 B span. Per-thread
//     body identical to the best round-5 shape: 8 rows, 2 batches of MLP=4.

#define S_LEN   8192
#define HALF_D  32
#define LOG2_THETA 13.287712379549449     // log2(10000)
#define TWO_PI    6.283185307179586476925
#define INV_2PI   0.159154943091895335769

__global__ void __launch_bounds__(512)
rope_fused2(const float4* __restrict__ x, float4* __restrict__ out,
            const int* __restrict__ token_position, int nrows) // nrows = B*H
{
    __shared__ float2 cs_sh[2 * HALF_D];   // 64 pairs: [sl][j]

    int tid = threadIdx.x;
    int s0  = blockIdx.x * 2;

    if (tid < 2 * HALF_D) {
        int sl = tid >> 5;                 // 0..1
        int j  = tid & 31;                 // frequency index
        float pos = (float)token_position[s0 + sl];
        float inv = (float)exp2(-(double)(2 * j) / 64.0 * LOG2_THETA);
        float ang = pos * inv;             // fp32 angle, reference rounding
        double a = (double)ang;
        double k = rint(a * INV_2PI);
        float  r = (float)(a - k * TWO_PI);    // |r| <= pi
        float sn, cn;
        sincosf(r, &sn, &cn);
        cs_sh[tid] = make_float2(cn, sn);
    }
    __syncthreads();

    int within = tid & 15;                 // float4 index within 64-elem row
    int sl     = (tid >> 4) & 1;           // which of the 2 positions
    int bh0    = tid >> 5;                 // 0..15
    // float4 view of cs_sh: entry (sl*16 + within) = pairs (2*within, 2*within+1)
    float4 cs = reinterpret_cast<const float4*>(cs_sh)[sl * 16 + within];

    const int rstride = 16 * S_LEN * 16;   // +16 bh rows, in float4 units
    int base = bh0 * (S_LEN * 16) + (s0 + sl) * 16 + within;

    #pragma unroll
    for (int batch = 0; batch < 2; batch++) {
        int i0 = base + batch * (4 * rstride);
        float4 v0 = x[i0];
        float4 v1 = x[i0 + rstride];
        float4 v2 = x[i0 + 2 * rstride];
        float4 v3 = x[i0 + 3 * rstride];

        float4 r0, r1, r2, r3;
        r0.x = v0.x * cs.x - v0.y * cs.y;  r0.y = v0.x * cs.y + v0.y * cs.x;
        r0.z = v0.z * cs.z - v0.w * cs.w;  r0.w = v0.z * cs.w + v0.w * cs.z;
        r1.x = v1.x * cs.x - v1.y * cs.y;  r1.y = v1.x * cs.y + v1.y * cs.x;
        r1.z = v1.z * cs.z - v1.w * cs.w;  r1.w = v1.z * cs.w + v1.w * cs.z;
        r2.x = v2.x * cs.x - v2.y * cs.y;  r2.y = v2.x * cs.y + v2.y * cs.x;
        r2.z = v2.z * cs.z - v2.w * cs.w;  r2.w = v2.z * cs.w + v2.w * cs.z;
        r3.x = v3.x * cs.x - v3.y * cs.y;  r3.y = v3.x * cs.y + v3.y * cs.x;
        r3.z = v3.z * cs.z - v3.w * cs.w;  r3.w = v3.z * cs.w + v3.w * cs.z;

        out[i0]               = r0;
        out[i0 + rstride]     = r1;
        out[i0 + 2 * rstride] = r2;
        out[i0 + 3 * rstride] = r3;
    }
}

extern "C" void kernel_launch(void* const* d_in, const int* in_sizes, int n_in,
                              void* d_out, int out_size) {
    const float* x   = (const float*)d_in[0];
    const int*   tok = (const int*)d_in[1];
    int n = in_sizes[0];           // 67,108,864 elements
    int P = in_sizes[1];           // 8192 positions (== S)
    int nrows = n / (P * 64);      // B*H = 128

    rope_fused2<<<P / 2, 512>>>((const float4*)x, (float4*)d_out, tok, nrows);
}